// round 1
// baseline (speedup 1.0000x reference)
#include <cuda_runtime.h>

// Problem constants
#define BP   128          // B*P
#define SEQ  1024         // S
#define DIM  1024         // D
#define NH   16           // heads
#define DH   64           // depth per head
#define SCALE 0.125f      // 1/sqrt(64)
#define SIGMA 0.1f

// ---------------- scratch (device globals; no allocation allowed) ------------
__device__ float g_qp[BP * DIM];
__device__ float g_kp[BP * DIM];
__device__ float g_vp[BP * DIM];
__device__ float g_part[32 * BP * DIM];   // per-s-chunk partial sums of attn·V
__device__ float g_zh[BP * DIM];          // merged attention output (mean_z)

// ---------------- projection GEMM: out[m][n] = x[m][:]·W[:][n] + b[n] + SIGMA*nz[m][n]
// M = 128 (all rows), block covers TN = 32 output columns, TK = 32.
// 128 threads, micro-tile 4 rows x 8 cols per thread -> compute-bound.
__device__ __forceinline__ void proj_body(const float* __restrict__ x,
                                          const float* __restrict__ W,
                                          const float* __restrict__ bias,
                                          const float* __restrict__ nz,
                                          float* __restrict__ out,
                                          int colBase)
{
    __shared__ float xs[32][132];   // [k][m], padded
    __shared__ float ws[32][32];    // [k][n]

    const int tid = threadIdx.x;          // 0..127
    const int tx  = tid & 3;              // 4 col-groups of 8
    const int ty  = tid >> 2;             // 32 row-groups of 4

    float acc[4][8];
#pragma unroll
    for (int i = 0; i < 4; i++)
#pragma unroll
        for (int j = 0; j < 8; j++) acc[i][j] = 0.f;

    for (int kk = 0; kk < DIM; kk += 32) {
        // x tile: 128 rows x 32 k  (1024 float4 / 128 threads = 8 each)
#pragma unroll
        for (int r = 0; r < 8; r++) {
            int i  = tid + r * 128;
            int m  = i >> 3;
            int kq = (i & 7) << 2;
            float4 v = *reinterpret_cast<const float4*>(x + m * DIM + kk + kq);
            xs[kq + 0][m] = v.x;
            xs[kq + 1][m] = v.y;
            xs[kq + 2][m] = v.z;
            xs[kq + 3][m] = v.w;
        }
        // W tile: 32 k x 32 n (256 float4 / 128 threads = 2 each)
#pragma unroll
        for (int r = 0; r < 2; r++) {
            int i  = tid + r * 128;
            int k  = i >> 3;
            int nq = (i & 7) << 2;
            *reinterpret_cast<float4*>(&ws[k][nq]) =
                *reinterpret_cast<const float4*>(W + (kk + k) * DIM + colBase + nq);
        }
        __syncthreads();

#pragma unroll 8
        for (int k = 0; k < 32; k++) {
            float4 a  = *reinterpret_cast<const float4*>(&xs[k][ty << 2]);
            float4 b0 = *reinterpret_cast<const float4*>(&ws[k][(tx << 3)]);
            float4 b1 = *reinterpret_cast<const float4*>(&ws[k][(tx << 3) + 4]);
            float av[4] = {a.x, a.y, a.z, a.w};
            float bv[8] = {b0.x, b0.y, b0.z, b0.w, b1.x, b1.y, b1.z, b1.w};
#pragma unroll
            for (int i = 0; i < 4; i++)
#pragma unroll
                for (int j = 0; j < 8; j++) acc[i][j] += av[i] * bv[j];
        }
        __syncthreads();
    }

    // epilogue
    int n0 = colBase + (tx << 3);
    float4 bL = *reinterpret_cast<const float4*>(bias + n0);
    float4 bH = *reinterpret_cast<const float4*>(bias + n0 + 4);
#pragma unroll
    for (int i = 0; i < 4; i++) {
        int m = (ty << 2) + i;
        float4 nL = *reinterpret_cast<const float4*>(nz + m * DIM + n0);
        float4 nH = *reinterpret_cast<const float4*>(nz + m * DIM + n0 + 4);
        float4 rL, rH;
        rL.x = acc[i][0] + bL.x + SIGMA * nL.x;
        rL.y = acc[i][1] + bL.y + SIGMA * nL.y;
        rL.z = acc[i][2] + bL.z + SIGMA * nL.z;
        rL.w = acc[i][3] + bL.w + SIGMA * nL.w;
        rH.x = acc[i][4] + bH.x + SIGMA * nH.x;
        rH.y = acc[i][5] + bH.y + SIGMA * nH.y;
        rH.z = acc[i][6] + bH.z + SIGMA * nH.z;
        rH.w = acc[i][7] + bH.w + SIGMA * nH.w;
        *reinterpret_cast<float4*>(out + m * DIM + n0)     = rL;
        *reinterpret_cast<float4*>(out + m * DIM + n0 + 4) = rH;
    }
}

__global__ void __launch_bounds__(128)
proj3_kernel(const float* __restrict__ q, const float* __restrict__ k,
             const float* __restrict__ v,
             const float* __restrict__ Wq, const float* __restrict__ Wk,
             const float* __restrict__ Wv,
             const float* __restrict__ bq, const float* __restrict__ bk,
             const float* __restrict__ bv,
             const float* __restrict__ nq, const float* __restrict__ nk,
             const float* __restrict__ nv)
{
    int mat = blockIdx.y;
    const float* x = (mat == 0) ? q  : (mat == 1) ? k  : v;
    const float* W = (mat == 0) ? Wq : (mat == 1) ? Wk : Wv;
    const float* b = (mat == 0) ? bq : (mat == 1) ? bk : bv;
    const float* n = (mat == 0) ? nq : (mat == 1) ? nk : nv;
    float* o       = (mat == 0) ? g_qp : (mat == 1) ? g_kp : g_vp;
    proj_body(x, W, b, n, o, blockIdx.x * 32);
}

__global__ void __launch_bounds__(128)
projZ_kernel(const float* __restrict__ Wz, const float* __restrict__ bz,
             const float* __restrict__ nz, float* __restrict__ z_out)
{
    proj_body(g_zh, Wz, bz, nz, z_out, blockIdx.x * 32);
}

// ---------------- copy K -> K_out (with slot write) + logits ----------------
// block: (chunk = blockIdx.x covers 32 s-rows, bp = blockIdx.y). 256 threads,
// thread t handles cols 4t..4t+3 (head h = t/16). Logits written into the
// attn output region (softmaxed in place later).
__global__ void __launch_bounds__(256)
copyK_kernel(const float* __restrict__ K, float* __restrict__ Kout,
             float* __restrict__ logits, const int* __restrict__ tptr)
{
    const int bp  = blockIdx.y;
    const int s0  = blockIdx.x * 32;
    const int tid = threadIdx.x;
    const int t   = *tptr;

    __shared__ float pds[32][256];   // per-s, per-thread partial dot

    float4 q4 = *reinterpret_cast<const float4*>(g_qp + bp * DIM + (tid << 2));
    const float* kprow = g_kp + bp * DIM;
    const float* Kb = K    + (size_t)bp * SEQ * DIM;
    float*       Ob = Kout + (size_t)bp * SEQ * DIM;

#pragma unroll 4
    for (int sl = 0; sl < 32; sl++) {
        int s = s0 + sl;
        const float* src = (s == t) ? kprow : (Kb + (size_t)s * DIM);
        float4 v = *reinterpret_cast<const float4*>(src + (tid << 2));
        *reinterpret_cast<float4*>(Ob + (size_t)s * DIM + (tid << 2)) = v;
        pds[sl][tid] = v.x * q4.x + v.y * q4.y + v.z * q4.z + v.w * q4.w;
    }
    __syncthreads();

    // 16 heads x 32 s = 512 reductions of 16 partials each
    for (int i = tid; i < 512; i += 256) {
        int h  = i & 15;
        int sl = i >> 4;
        float sum = 0.f;
#pragma unroll
        for (int j = 0; j < 16; j++) sum += pds[sl][(h << 4) + j];
        logits[((size_t)(bp * NH + h)) * SEQ + s0 + sl] = sum * SCALE;
    }
}

// ---------------- softmax in place over attn region (rows of 1024) ----------
__global__ void __launch_bounds__(256)
softmax_kernel(float* __restrict__ attn)
{
    int row  = blockIdx.x * 8 + (threadIdx.x >> 5);   // 2048 rows
    int lane = threadIdx.x & 31;
    float* p = attn + (size_t)row * SEQ;

    float v[32];
    float m = -1e30f;
#pragma unroll
    for (int i = 0; i < 32; i++) { v[i] = p[lane + (i << 5)]; m = fmaxf(m, v[i]); }
#pragma unroll
    for (int o = 16; o > 0; o >>= 1) m = fmaxf(m, __shfl_xor_sync(0xffffffffu, m, o));
    float sum = 0.f;
#pragma unroll
    for (int i = 0; i < 32; i++) { v[i] = __expf(v[i] - m); sum += v[i]; }
#pragma unroll
    for (int o = 16; o > 0; o >>= 1) sum += __shfl_xor_sync(0xffffffffu, sum, o);
    float inv = 1.f / sum;
#pragma unroll
    for (int i = 0; i < 32; i++) p[lane + (i << 5)] = v[i] * inv;
}

// ---------------- copy V -> V_out (slot write) + attn-weighted partials -----
__global__ void __launch_bounds__(256)
copyV_kernel(const float* __restrict__ V, float* __restrict__ Vout,
             const float* __restrict__ attn, const int* __restrict__ tptr)
{
    const int bp  = blockIdx.y;
    const int s0  = blockIdx.x * 32;
    const int tid = threadIdx.x;
    const int t   = *tptr;

    __shared__ float as[NH][32];
    for (int i = tid; i < NH * 32; i += 256) {
        int h  = i >> 5;
        int sl = i & 31;
        as[h][sl] = attn[((size_t)(bp * NH + h)) * SEQ + s0 + sl];
    }
    __syncthreads();

    const float* vprow = g_vp + bp * DIM;
    const float* Vb = V    + (size_t)bp * SEQ * DIM;
    float*       Ob = Vout + (size_t)bp * SEQ * DIM;

    const int h = tid >> 4;   // head of cols 4t..4t+3
    float4 acc = make_float4(0.f, 0.f, 0.f, 0.f);

#pragma unroll 4
    for (int sl = 0; sl < 32; sl++) {
        int s = s0 + sl;
        const float* src = (s == t) ? vprow : (Vb + (size_t)s * DIM);
        float4 v = *reinterpret_cast<const float4*>(src + (tid << 2));
        *reinterpret_cast<float4*>(Ob + (size_t)s * DIM + (tid << 2)) = v;
        float a = as[h][sl];
        acc.x += a * v.x; acc.y += a * v.y; acc.z += a * v.z; acc.w += a * v.w;
    }
    *reinterpret_cast<float4*>(g_part + ((size_t)blockIdx.x * BP + bp) * DIM + (tid << 2)) = acc;
}

// ---------------- reduce the 32 s-chunk partials into g_zh ------------------
__global__ void __launch_bounds__(256)
reduce_kernel()
{
    int i = blockIdx.x * 256 + threadIdx.x;   // over BP*DIM = 131072
    float s = 0.f;
#pragma unroll
    for (int c = 0; c < 32; c++) s += g_part[c * (BP * DIM) + i];
    g_zh[i] = s;
}

// ---------------- launch ----------------------------------------------------
extern "C" void kernel_launch(void* const* d_in, const int* in_sizes, int n_in,
                              void* d_out, int out_size)
{
    const float* q   = (const float*)d_in[0];
    const float* k   = (const float*)d_in[1];
    const float* v   = (const float*)d_in[2];
    const float* Kin = (const float*)d_in[3];
    const float* Vin = (const float*)d_in[4];
    const float* Wq  = (const float*)d_in[5];
    const float* bq  = (const float*)d_in[6];
    const float* Wk  = (const float*)d_in[7];
    const float* bk  = (const float*)d_in[8];
    const float* Wv  = (const float*)d_in[9];
    const float* bv  = (const float*)d_in[10];
    const float* Wz  = (const float*)d_in[11];
    const float* bz  = (const float*)d_in[12];
    const float* nq  = (const float*)d_in[13];
    const float* nk  = (const float*)d_in[14];
    const float* nv  = (const float*)d_in[15];
    const float* nz  = (const float*)d_in[16];
    const int* tstep = (const int*)d_in[17];

    float* out   = (float*)d_out;
    float* z_out = out;                                       // 128*1024
    float* K_out = out + (size_t)BP * DIM;                    // 128*1024*1024
    float* V_out = K_out + (size_t)BP * SEQ * DIM;
    float* attn  = V_out + (size_t)BP * SEQ * DIM;            // 128*16*1024

    // 1. projections q/k/v (+bias +sigma*noise)
    proj3_kernel<<<dim3(32, 3), 128>>>(q, k, v, Wq, Wk, Wv, bq, bk, bv, nq, nk, nv);
    // 2. K copy (slot write at t) fused with logits
    copyK_kernel<<<dim3(32, BP), 256>>>(Kin, K_out, attn, tstep);
    // 3. softmax in place
    softmax_kernel<<<256, 256>>>(attn);
    // 4. V copy (slot write at t) fused with attn-weighted partial sums
    copyV_kernel<<<dim3(32, BP), 256>>>(Vin, V_out, attn, tstep);
    // 5. reduce partials -> zh
    reduce_kernel<<<512, 256>>>();
    // 6. output projection z
    projZ_kernel<<<dim3(32, 1), 128>>>(Wz, bz, nz, z_out);
}